// round 4
// baseline (speedup 1.0000x reference)
#include <cuda_runtime.h>

#define NB    16
#define NCP   64
#define NTPL  2048
#define HD    10
#define NSTEP 6
#define DTC   0.2f
#define LOG2E 1.4426950408889634f

typedef unsigned long long ull;

// ---- scratch (static device globals; no allocation) ----
__device__ float2 g_P[NSTEP + 1][NB * NCP];
__device__ float2 g_Q[NSTEP + 1][NB * NCP];
__device__ unsigned g_bar_count;   // zero-initialized; self-resetting
__device__ unsigned g_bar_gen;     // monotonically increasing across replays

// ---------------- packed f32x2 helpers ----------------
__device__ __forceinline__ ull pack2(float lo, float hi) {
    ull d; asm("mov.b64 %0, {%1,%2};" : "=l"(d) : "f"(lo), "f"(hi)); return d;
}
__device__ __forceinline__ void unpack2(ull d, float& lo, float& hi) {
    asm("mov.b64 {%0,%1}, %2;" : "=f"(lo), "=f"(hi) : "l"(d));
}
__device__ __forceinline__ ull fma2(ull a, ull b, ull c) {
    ull d; asm("fma.rn.f32x2 %0, %1, %2, %3;" : "=l"(d) : "l"(a), "l"(b), "l"(c)); return d;
}
__device__ __forceinline__ ull add2(ull a, ull b) {
    ull d; asm("add.rn.f32x2 %0, %1, %2;" : "=l"(d) : "l"(a), "l"(b)); return d;
}
__device__ __forceinline__ float tanhfast(float x) {
    float y; asm("tanh.approx.f32 %0, %1;" : "=f"(y) : "f"(x)); return y;
}
__device__ __forceinline__ float ex2f(float x) {
    float y; asm("ex2.approx.f32 %0, %1;" : "=f"(y) : "f"(x)); return y;
}

// ---------------- software grid barrier (all CTAs resident) ----------------
__device__ __forceinline__ void grid_bar() {
    __syncthreads();
    if (threadIdx.x == 0) {
        __threadfence();
        unsigned gen = *(volatile unsigned*)&g_bar_gen;
        unsigned prev = atomicAdd(&g_bar_count, 1u);
        if (prev == gridDim.x - 1) {
            g_bar_count = 0;
            __threadfence();
            atomicExch(&g_bar_gen, gen + 1u);
        } else {
            while (*(volatile unsigned*)&g_bar_gen == gen) { }
            __threadfence();
        }
    }
    __syncthreads();
}

// ------------------------------------------------------------------
// MLP forward + 2-tangent JVP (tangent dirs = rows da, db of W1)
// ------------------------------------------------------------------
__device__ __forceinline__ void mlp_jac(
    float z0, float z1, float z2, float z3, int da, int db,
    const float* __restrict__ sW1, const float* __restrict__ sb1,
    const float* __restrict__ sW2, const float* __restrict__ sb2,
    const float* __restrict__ sW3, const float* __restrict__ sb3,
    float o[3], float ja[3], float jb[3]) {
    float h1[HD], ta[HD], tb[HD];
#pragma unroll
    for (int n = 0; n < HD; n++) {
        float u = sb1[n] + z0 * sW1[n] + z1 * sW1[10 + n] + z2 * sW1[20 + n] + z3 * sW1[30 + n];
        float h = tanhfast(u);
        float g = 1.0f - h * h;
        h1[n] = h;
        ta[n] = g * sW1[da * 10 + n];
        tb[n] = g * sW1[db * 10 + n];
    }
    float u2[HD], s2a[HD], s2b[HD];
#pragma unroll
    for (int m = 0; m < HD; m++) { u2[m] = sb2[m]; s2a[m] = 0.f; s2b[m] = 0.f; }
#pragma unroll
    for (int n = 0; n < HD; n++) {
        float h = h1[n], aa = ta[n], bb = tb[n];
#pragma unroll
        for (int m = 0; m < HD; m++) {
            float w = sW2[n * 10 + m];
            u2[m] += h * w;
            s2a[m] += aa * w;
            s2b[m] += bb * w;
        }
    }
#pragma unroll
    for (int c = 0; c < 3; c++) { o[c] = sb3[c]; ja[c] = 0.f; jb[c] = 0.f; }
#pragma unroll
    for (int m = 0; m < HD; m++) {
        float h = tanhfast(u2[m]);
        float g = 1.0f - h * h;
        float aa = s2a[m] * g, bb = s2b[m] * g;
#pragma unroll
        for (int c = 0; c < 3; c++) {
            float w = sW3[m * 3 + c];
            o[c] += h * w;
            ja[c] += aa * w;
            jb[c] += bb * w;
        }
    }
}

// ------------------------------------------------------------------
// all 6 shooting steps in ONE persistent kernel (512 CTAs x 128 thr).
// ------------------------------------------------------------------
__global__ void __launch_bounds__(128, 4) shoot_all(
    const float* __restrict__ q0, const float* __restrict__ cp,
    const float* __restrict__ W1, const float* __restrict__ b1,
    const float* __restrict__ W2, const float* __restrict__ b2,
    const float* __restrict__ W3, const float* __restrict__ b3) {
    __shared__ float sW1[40], sb1[10], sW2[100], sb2[10], sW3[30], sb3[3];
    __shared__ float red[2][4][4];
    int t = threadIdx.x;
    for (int i = t; i < 40; i += 128) sW1[i] = W1[i];
    for (int i = t; i < 100; i += 128) sW2[i] = W2[i];
    for (int i = t; i < 30; i += 128) sW3[i] = W3[i];
    if (t < 10) { sb1[t] = b1[t]; sb2[t] = b2[t]; }
    if (t < 3) sb3[t] = b3[t];
    __syncthreads();

    int c = blockIdx.x;
    int b = c >> 5;
    int a0 = (c & 31) << 1;
    int j = t & 63, half = t >> 6;
    const float2* cp2 = (const float2*)cp;
    const float2* q02 = (const float2*)q0;

    for (int k = 0; k < NSTEP; k++) {
        float2 pj, qj;
        if (k == 0) { pj = cp2[j]; qj = q02[b * NCP + j]; }
        else        { pj = g_P[k][b * NCP + j]; qj = g_Q[k][b * NCP + j]; }

        float2 pas[2], qas[2];
#pragma unroll
        for (int aa = 0; aa < 2; aa++) {
            int a = a0 + aa;
            float2 pa, qa;
            if (k == 0) { pa = cp2[a]; qa = q02[b * NCP + a]; }
            else        { pa = g_P[k][b * NCP + a]; qa = g_Q[k][b * NCP + a]; }
            pas[aa] = pa; qas[aa] = qa;

            float z0 = half ? pj.x : pa.x, z1 = half ? pj.y : pa.y;
            float z2 = half ? pa.x : pj.x, z3 = half ? pa.y : pj.y;
            int da = half * 2, db = half * 2 + 1;

            float o[3], ja[3], jb[3];
            mlp_jac(z0, z1, z2, z3, da, db, sW1, sb1, sW2, sb2, sW3, sb3, o, ja, jb);

            float ea = __expf(o[1]), eb = __expf(o[2]);
            float vqx = 0.5f * (ea * qj.x + o[0] * qj.y);
            float vqy = 0.5f * (o[0] * qj.x + eb * qj.y);
            float cw = qa.x * qj.y + qa.y * qj.x;
            float w1 = ea * (qa.x * qj.x), w2 = eb * (qa.y * qj.y);
            float gpx = 0.5f * (cw * ja[0] + w1 * ja[1] + w2 * ja[2]);
            float gpy = 0.5f * (cw * jb[0] + w1 * jb[1] + w2 * jb[2]);

#pragma unroll
            for (int off = 16; off > 0; off >>= 1) {
                vqx += __shfl_down_sync(0xffffffffu, vqx, off);
                vqy += __shfl_down_sync(0xffffffffu, vqy, off);
                gpx += __shfl_down_sync(0xffffffffu, gpx, off);
                gpy += __shfl_down_sync(0xffffffffu, gpy, off);
            }
            if ((t & 31) == 0) {
                int w = t >> 5;
                red[aa][w][0] = vqx; red[aa][w][1] = vqy;
                red[aa][w][2] = gpx; red[aa][w][3] = gpy;
            }
        }
        __syncthreads();
        if (t == 0) {
#pragma unroll
            for (int aa = 0; aa < 2; aa++) {
                int a = a0 + aa;
                float VX = red[aa][0][0] + red[aa][1][0] + red[aa][2][0] + red[aa][3][0];
                float VY = red[aa][0][1] + red[aa][1][1] + red[aa][2][1] + red[aa][3][1];
                float GX = red[aa][0][2] + red[aa][1][2] + red[aa][2][2] + red[aa][3][2];
                float GY = red[aa][0][3] + red[aa][1][3] + red[aa][2][3] + red[aa][3][3];
                g_P[k + 1][b * NCP + a] = make_float2(pas[aa].x + DTC * VX, pas[aa].y + DTC * VY);
                g_Q[k + 1][b * NCP + a] = make_float2(qas[aa].x - DTC * GX, qas[aa].y - DTC * GY);
                if (k == 0) {
                    g_P[0][b * NCP + a] = pas[aa];
                    g_Q[0][b * NCP + a] = qas[aa];
                }
            }
        }
        if (k < NSTEP - 1) grid_bar();
    }
}

// ------------------------------------------------------------------
// packed forward MLP; W2 read from SHARED memory (broadcast LDS.64),
// layer-3 weights in registers; W3 cols 1,2 prescaled by log2e.
// ------------------------------------------------------------------
__device__ __forceinline__ void mlp2(
    const ull u1p[5], const ull* sW2p, const ull b2p[5],
    const float W3c0[10], const ull W3p12[10],
    float b3c0, ull b3p12,
    float& o0, ull& o12) {
    ull u2p[5];
#pragma unroll
    for (int i = 0; i < 5; i++) u2p[i] = b2p[i];
#pragma unroll
    for (int i = 0; i < 5; i++) {
        float lo, hi; unpack2(u1p[i], lo, hi);
        float h0 = tanhfast(lo), h1 = tanhfast(hi);
        ull hp0 = pack2(h0, h0), hp1 = pack2(h1, h1);
        int n0 = (2 * i) * 5, n1 = (2 * i + 1) * 5;
#pragma unroll
        for (int m = 0; m < 5; m++) u2p[m] = fma2(hp0, sW2p[n0 + m], u2p[m]);
#pragma unroll
        for (int m = 0; m < 5; m++) u2p[m] = fma2(hp1, sW2p[n1 + m], u2p[m]);
    }
    o0 = b3c0; o12 = b3p12;
#pragma unroll
    for (int i = 0; i < 5; i++) {
        float lo, hi; unpack2(u2p[i], lo, hi);
        float h0 = tanhfast(lo), h1 = tanhfast(hi);
        ull hp0 = pack2(h0, h0), hp1 = pack2(h1, h1);
        o12 = fma2(hp0, W3p12[2 * i], o12);
        o12 = fma2(hp1, W3p12[2 * i + 1], o12);
        o0 = fmaf(h1, W3c0[2 * i + 1], fmaf(h0, W3c0[2 * i], o0));
    }
}

// ------------------------------------------------------------------
// all 7 flow steps in ONE kernel: x in registers across steps.
// 1024 CTAs x 128 thr = 32 points x 4 j-splits, j interleaved mod 4.
// W2 lives in shared memory -> ~100 fewer regs -> 3 CTAs/SM.
// ------------------------------------------------------------------
__global__ void __launch_bounds__(128, 3) flow_all(
    const float* __restrict__ tpl, float* __restrict__ dout,
    const float* __restrict__ W1, const float* __restrict__ b1,
    const float* __restrict__ W2, const float* __restrict__ b2,
    const float* __restrict__ W3, const float* __restrict__ b3) {
    __shared__ ull sA[NCP][5];   // packed b1 + pj.W1[0:2]
    __shared__ ull sB[NCP][5];   // packed      pj.W1[2:4]
    __shared__ float sQx[NCP], sQy[NCP];   // 0.5*q folded in
    __shared__ float sW1[40], sb1[10];
    __shared__ ull sW2p[50];     // W2 packed by output pair
    int t = threadIdx.x;
    int blk = blockIdx.x;
    int b = blk >> 6;
    int pt0 = (blk & 63) << 5;
    if (t < 40) sW1[t] = W1[t];
    if (t < 10) sb1[t] = b1[t];
    if (t >= 64 && t < 114) sW2p[t - 64] = ((const ull*)W2)[t - 64];

    // small weights resident in registers for the whole kernel
    const ull* b2v = (const ull*)b2;
    ull b2p[5];
#pragma unroll
    for (int i = 0; i < 5; i++) b2p[i] = __ldg(&b2v[i]);
    float W3c0[10];
    ull W3p12[10];
#pragma unroll
    for (int m = 0; m < HD; m++) {
        W3c0[m] = __ldg(&W3[m * 3 + 0]);
        W3p12[m] = pack2(LOG2E * __ldg(&W3[m * 3 + 1]), LOG2E * __ldg(&W3[m * 3 + 2]));
    }
    float b3c0 = __ldg(&b3[0]);
    ull b3p12 = pack2(LOG2E * __ldg(&b3[1]), LOG2E * __ldg(&b3[2]));

    int lp = t >> 2, quarter = t & 3;
    int i0 = pt0 + lp;
    float2 x = __ldg(&((const float2*)tpl)[i0]);

    for (int k = 0; k <= NSTEP; k++) {
        __syncthreads();   // prior iteration's reads of sA/sB done
        if (t < NCP) {
            float2 p = g_P[k][b * NCP + t];
            float2 q = g_Q[k][b * NCP + t];
#pragma unroll
            for (int i = 0; i < 5; i++) {
                int n0 = 2 * i, n1 = n0 + 1;
                sA[t][i] = pack2(sb1[n0] + p.x * sW1[n0] + p.y * sW1[10 + n0],
                                 sb1[n1] + p.x * sW1[n1] + p.y * sW1[10 + n1]);
                sB[t][i] = pack2(p.x * sW1[20 + n0] + p.y * sW1[30 + n0],
                                 p.x * sW1[20 + n1] + p.y * sW1[30 + n1]);
            }
            sQx[t] = 0.5f * q.x;
            sQy[t] = 0.5f * q.y;
        }
        // per-thread layer-1 parts for current x
        ull axp[5], bxp[5];
#pragma unroll
        for (int i = 0; i < 5; i++) {
            int n0 = 2 * i, n1 = n0 + 1;
            axp[i] = pack2(sb1[n0] + x.x * sW1[n0] + x.y * sW1[10 + n0],
                           sb1[n1] + x.x * sW1[n1] + x.y * sW1[10 + n1]);
            bxp[i] = pack2(x.x * sW1[20 + n0] + x.y * sW1[30 + n0],
                           x.x * sW1[20 + n1] + x.y * sW1[30 + n1]);
        }
        __syncthreads();

        float vx = 0.f, vy = 0.f;
#pragma unroll 1
        for (int jj = 0; jj < 16; jj++) {
            int j = (jj << 2) | quarter;
            ull u1[5];
#pragma unroll
            for (int i = 0; i < 5; i++) u1[i] = add2(axp[i], sB[j][i]);  // m(x, pj)
            float a0; ull a12;
            mlp2(u1, sW2p, b2p, W3c0, W3p12, b3c0, b3p12, a0, a12);
#pragma unroll
            for (int i = 0; i < 5; i++) u1[i] = add2(sA[j][i], bxp[i]);  // m(pj, x)
            float c0; ull c12;
            mlp2(u1, sW2p, b2p, W3c0, W3p12, b3c0, b3p12, c0, c12);
            float a1, a2, c1, c2;
            unpack2(a12, a1, a2);
            unpack2(c12, c1, c2);
            float s0 = a0 + c0;
            float qx2 = sQx[j], qy2 = sQy[j];
            vx = fmaf(ex2f(a1), qx2, vx);
            vx = fmaf(ex2f(c1), qx2, vx);
            vx = fmaf(s0, qy2, vx);
            vy = fmaf(s0, qx2, vy);
            vy = fmaf(ex2f(a2), qy2, vy);
            vy = fmaf(ex2f(c2), qy2, vy);
        }
        vx += __shfl_xor_sync(0xffffffffu, vx, 1);
        vy += __shfl_xor_sync(0xffffffffu, vy, 1);
        vx += __shfl_xor_sync(0xffffffffu, vx, 2);
        vy += __shfl_xor_sync(0xffffffffu, vy, 2);
        x.x = fmaf(DTC, vx, x.x);
        x.y = fmaf(DTC, vy, x.y);
    }
    if (quarter == 0) ((float2*)dout)[b * NTPL + i0] = x;
}

// ------------------------------------------------------------------
extern "C" void kernel_launch(void* const* d_in, const int* in_sizes, int n_in,
                              void* d_out, int out_size) {
    const float* q0  = (const float*)d_in[0];
    const float* tpl = (const float*)d_in[1];
    const float* cp  = (const float*)d_in[2];
    const float* W1  = (const float*)d_in[3];
    const float* b1  = (const float*)d_in[4];
    const float* W2  = (const float*)d_in[5];
    const float* b2  = (const float*)d_in[6];
    const float* W3  = (const float*)d_in[7];
    const float* b3  = (const float*)d_in[8];
    float* out = (float*)d_out;
    (void)in_sizes; (void)n_in; (void)out_size;

    shoot_all<<<512, 128>>>(q0, cp, W1, b1, W2, b2, W3, b3);
    flow_all<<<NB * (NTPL / 32), 128>>>(tpl, out, W1, b1, W2, b2, W3, b3);
}

// round 5
// speedup vs baseline: 1.3828x; 1.3828x over previous
#include <cuda_runtime.h>

#define NB    16
#define NCP   64
#define NTPL  2048
#define HD    10
#define NSTEP 6
#define DTC   0.2f
#define LOG2E 1.4426950408889634f

typedef unsigned long long ull;

// ---- scratch (static device globals; no allocation) ----
__device__ float2 g_P[NSTEP + 1][NB * NCP];
__device__ float2 g_Q[NSTEP + 1][NB * NCP];
__device__ unsigned g_bar_count;   // zero-initialized; self-resetting
__device__ unsigned g_bar_gen;     // monotonically increasing across replays

// ---------------- packed f32x2 helpers ----------------
__device__ __forceinline__ ull pack2(float lo, float hi) {
    ull d; asm("mov.b64 %0, {%1,%2};" : "=l"(d) : "f"(lo), "f"(hi)); return d;
}
__device__ __forceinline__ void unpack2(ull d, float& lo, float& hi) {
    asm("mov.b64 {%0,%1}, %2;" : "=f"(lo), "=f"(hi) : "l"(d));
}
__device__ __forceinline__ ull fma2(ull a, ull b, ull c) {
    ull d; asm("fma.rn.f32x2 %0, %1, %2, %3;" : "=l"(d) : "l"(a), "l"(b), "l"(c)); return d;
}
__device__ __forceinline__ ull add2(ull a, ull b) {
    ull d; asm("add.rn.f32x2 %0, %1, %2;" : "=l"(d) : "l"(a), "l"(b)); return d;
}
__device__ __forceinline__ float tanhfast(float x) {
    float y; asm("tanh.approx.f32 %0, %1;" : "=f"(y) : "f"(x)); return y;
}
__device__ __forceinline__ float ex2f(float x) {
    float y; asm("ex2.approx.f32 %0, %1;" : "=f"(y) : "f"(x)); return y;
}

// ---------------- software grid barrier (all CTAs resident) ----------------
__device__ __forceinline__ void grid_bar() {
    __syncthreads();
    if (threadIdx.x == 0) {
        __threadfence();
        unsigned gen = *(volatile unsigned*)&g_bar_gen;
        unsigned prev = atomicAdd(&g_bar_count, 1u);
        if (prev == gridDim.x - 1) {
            g_bar_count = 0;
            __threadfence();
            atomicExch(&g_bar_gen, gen + 1u);
        } else {
            while (*(volatile unsigned*)&g_bar_gen == gen) { }
            __threadfence();
        }
    }
    __syncthreads();
}

// ------------------------------------------------------------------
// MLP forward + 2-tangent JVP (tangent dirs = rows da, db of W1)
// ------------------------------------------------------------------
__device__ __forceinline__ void mlp_jac(
    float z0, float z1, float z2, float z3, int da, int db,
    const float* __restrict__ sW1, const float* __restrict__ sb1,
    const float* __restrict__ sW2, const float* __restrict__ sb2,
    const float* __restrict__ sW3, const float* __restrict__ sb3,
    float o[3], float ja[3], float jb[3]) {
    float h1[HD], ta[HD], tb[HD];
#pragma unroll
    for (int n = 0; n < HD; n++) {
        float u = sb1[n] + z0 * sW1[n] + z1 * sW1[10 + n] + z2 * sW1[20 + n] + z3 * sW1[30 + n];
        float h = tanhfast(u);
        float g = 1.0f - h * h;
        h1[n] = h;
        ta[n] = g * sW1[da * 10 + n];
        tb[n] = g * sW1[db * 10 + n];
    }
    float u2[HD], s2a[HD], s2b[HD];
#pragma unroll
    for (int m = 0; m < HD; m++) { u2[m] = sb2[m]; s2a[m] = 0.f; s2b[m] = 0.f; }
#pragma unroll
    for (int n = 0; n < HD; n++) {
        float h = h1[n], aa = ta[n], bb = tb[n];
#pragma unroll
        for (int m = 0; m < HD; m++) {
            float w = sW2[n * 10 + m];
            u2[m] += h * w;
            s2a[m] += aa * w;
            s2b[m] += bb * w;
        }
    }
#pragma unroll
    for (int c = 0; c < 3; c++) { o[c] = sb3[c]; ja[c] = 0.f; jb[c] = 0.f; }
#pragma unroll
    for (int m = 0; m < HD; m++) {
        float h = tanhfast(u2[m]);
        float g = 1.0f - h * h;
        float aa = s2a[m] * g, bb = s2b[m] * g;
#pragma unroll
        for (int c = 0; c < 3; c++) {
            float w = sW3[m * 3 + c];
            o[c] += h * w;
            ja[c] += aa * w;
            jb[c] += bb * w;
        }
    }
}

// ------------------------------------------------------------------
// all 6 shooting steps in ONE persistent kernel (512 CTAs x 128 thr).
// ------------------------------------------------------------------
__global__ void __launch_bounds__(128, 4) shoot_all(
    const float* __restrict__ q0, const float* __restrict__ cp,
    const float* __restrict__ W1, const float* __restrict__ b1,
    const float* __restrict__ W2, const float* __restrict__ b2,
    const float* __restrict__ W3, const float* __restrict__ b3) {
    __shared__ float sW1[40], sb1[10], sW2[100], sb2[10], sW3[30], sb3[3];
    __shared__ float red[2][4][4];
    int t = threadIdx.x;
    for (int i = t; i < 40; i += 128) sW1[i] = W1[i];
    for (int i = t; i < 100; i += 128) sW2[i] = W2[i];
    for (int i = t; i < 30; i += 128) sW3[i] = W3[i];
    if (t < 10) { sb1[t] = b1[t]; sb2[t] = b2[t]; }
    if (t < 3) sb3[t] = b3[t];
    __syncthreads();

    int c = blockIdx.x;
    int b = c >> 5;
    int a0 = (c & 31) << 1;
    int j = t & 63, half = t >> 6;
    const float2* cp2 = (const float2*)cp;
    const float2* q02 = (const float2*)q0;

    for (int k = 0; k < NSTEP; k++) {
        float2 pj, qj;
        if (k == 0) { pj = cp2[j]; qj = q02[b * NCP + j]; }
        else        { pj = g_P[k][b * NCP + j]; qj = g_Q[k][b * NCP + j]; }

        float2 pas[2], qas[2];
#pragma unroll
        for (int aa = 0; aa < 2; aa++) {
            int a = a0 + aa;
            float2 pa, qa;
            if (k == 0) { pa = cp2[a]; qa = q02[b * NCP + a]; }
            else        { pa = g_P[k][b * NCP + a]; qa = g_Q[k][b * NCP + a]; }
            pas[aa] = pa; qas[aa] = qa;

            float z0 = half ? pj.x : pa.x, z1 = half ? pj.y : pa.y;
            float z2 = half ? pa.x : pj.x, z3 = half ? pa.y : pj.y;
            int da = half * 2, db = half * 2 + 1;

            float o[3], ja[3], jb[3];
            mlp_jac(z0, z1, z2, z3, da, db, sW1, sb1, sW2, sb2, sW3, sb3, o, ja, jb);

            float ea = __expf(o[1]), eb = __expf(o[2]);
            float vqx = 0.5f * (ea * qj.x + o[0] * qj.y);
            float vqy = 0.5f * (o[0] * qj.x + eb * qj.y);
            float cw = qa.x * qj.y + qa.y * qj.x;
            float w1 = ea * (qa.x * qj.x), w2 = eb * (qa.y * qj.y);
            float gpx = 0.5f * (cw * ja[0] + w1 * ja[1] + w2 * ja[2]);
            float gpy = 0.5f * (cw * jb[0] + w1 * jb[1] + w2 * jb[2]);

#pragma unroll
            for (int off = 16; off > 0; off >>= 1) {
                vqx += __shfl_down_sync(0xffffffffu, vqx, off);
                vqy += __shfl_down_sync(0xffffffffu, vqy, off);
                gpx += __shfl_down_sync(0xffffffffu, gpx, off);
                gpy += __shfl_down_sync(0xffffffffu, gpy, off);
            }
            if ((t & 31) == 0) {
                int w = t >> 5;
                red[aa][w][0] = vqx; red[aa][w][1] = vqy;
                red[aa][w][2] = gpx; red[aa][w][3] = gpy;
            }
        }
        __syncthreads();
        if (t == 0) {
#pragma unroll
            for (int aa = 0; aa < 2; aa++) {
                int a = a0 + aa;
                float VX = red[aa][0][0] + red[aa][1][0] + red[aa][2][0] + red[aa][3][0];
                float VY = red[aa][0][1] + red[aa][1][1] + red[aa][2][1] + red[aa][3][1];
                float GX = red[aa][0][2] + red[aa][1][2] + red[aa][2][2] + red[aa][3][2];
                float GY = red[aa][0][3] + red[aa][1][3] + red[aa][2][3] + red[aa][3][3];
                g_P[k + 1][b * NCP + a] = make_float2(pas[aa].x + DTC * VX, pas[aa].y + DTC * VY);
                g_Q[k + 1][b * NCP + a] = make_float2(qas[aa].x - DTC * GX, qas[aa].y - DTC * GY);
                if (k == 0) {
                    g_P[0][b * NCP + a] = pas[aa];
                    g_Q[0][b * NCP + a] = qas[aa];
                }
            }
        }
        if (k < NSTEP - 1) grid_bar();
    }
}

// ------------------------------------------------------------------
// packed forward MLP: weights in REGISTERS (round-4 lesson: no smem in
// the hot path); W3 cols 1,2 prescaled by log2e so o12 feeds ex2 directly.
// ------------------------------------------------------------------
__device__ __forceinline__ void mlp2(
    const ull u1p[5], const ull W2p[50], const ull b2p[5],
    const float W3c0[10], const ull W3p12[10],
    float b3c0, ull b3p12,
    float& o0, ull& o12) {
    ull u2p[5];
#pragma unroll
    for (int i = 0; i < 5; i++) u2p[i] = b2p[i];
#pragma unroll
    for (int i = 0; i < 5; i++) {
        float lo, hi; unpack2(u1p[i], lo, hi);
        float h0 = tanhfast(lo), h1 = tanhfast(hi);
        ull hp0 = pack2(h0, h0), hp1 = pack2(h1, h1);
        int n0 = (2 * i) * 5, n1 = (2 * i + 1) * 5;
#pragma unroll
        for (int m = 0; m < 5; m++) u2p[m] = fma2(hp0, W2p[n0 + m], u2p[m]);
#pragma unroll
        for (int m = 0; m < 5; m++) u2p[m] = fma2(hp1, W2p[n1 + m], u2p[m]);
    }
    o0 = b3c0; o12 = b3p12;
#pragma unroll
    for (int i = 0; i < 5; i++) {
        float lo, hi; unpack2(u2p[i], lo, hi);
        float h0 = tanhfast(lo), h1 = tanhfast(hi);
        ull hp0 = pack2(h0, h0), hp1 = pack2(h1, h1);
        o12 = fma2(hp0, W3p12[2 * i], o12);
        o12 = fma2(hp1, W3p12[2 * i + 1], o12);
        o0 = fmaf(h1, W3c0[2 * i + 1], fmaf(h0, W3c0[2 * i], o0));
    }
}

// ------------------------------------------------------------------
// all 7 flow steps in ONE kernel: x in registers across steps.
// 1024 CTAs x 128 thr = 32 points x 4 j-splits, j interleaved mod 4.
// unroll 2 on the j-loop: two independent pair-iterations in flight to
// cover tanh/fma2-chain latency at 2 warps/SMSP occupancy.
// ------------------------------------------------------------------
__global__ void __launch_bounds__(128, 2) flow_all(
    const float* __restrict__ tpl, float* __restrict__ dout,
    const float* __restrict__ W1, const float* __restrict__ b1,
    const float* __restrict__ W2, const float* __restrict__ b2,
    const float* __restrict__ W3, const float* __restrict__ b3) {
    __shared__ ull sA[NCP][5];   // packed b1 + pj.W1[0:2]
    __shared__ ull sB[NCP][5];   // packed      pj.W1[2:4]
    __shared__ ull sQp[NCP];     // packed (0.5*qx, 0.5*qy)
    __shared__ float sW1[40], sb1[10];
    int t = threadIdx.x;
    int blk = blockIdx.x;
    int b = blk >> 6;
    int pt0 = (blk & 63) << 5;
    if (t < 40) sW1[t] = W1[t];
    if (t < 10) sb1[t] = b1[t];

    // weights resident in registers for the whole kernel
    const ull* W2v = (const ull*)W2;
    const ull* b2v = (const ull*)b2;
    ull W2p[50];
#pragma unroll
    for (int i = 0; i < 50; i++) W2p[i] = __ldg(&W2v[i]);
    ull b2p[5];
#pragma unroll
    for (int i = 0; i < 5; i++) b2p[i] = __ldg(&b2v[i]);
    float W3c0[10];
    ull W3p12[10];
#pragma unroll
    for (int m = 0; m < HD; m++) {
        W3c0[m] = __ldg(&W3[m * 3 + 0]);
        W3p12[m] = pack2(LOG2E * __ldg(&W3[m * 3 + 1]), LOG2E * __ldg(&W3[m * 3 + 2]));
    }
    float b3c0 = __ldg(&b3[0]);
    ull b3p12 = pack2(LOG2E * __ldg(&b3[1]), LOG2E * __ldg(&b3[2]));

    int lp = t >> 2, quarter = t & 3;
    int i0 = pt0 + lp;
    float2 x = __ldg(&((const float2*)tpl)[i0]);

    for (int k = 0; k <= NSTEP; k++) {
        __syncthreads();   // prior iteration's reads of sA/sB done
        if (t < NCP) {
            float2 p = g_P[k][b * NCP + t];
            float2 q = g_Q[k][b * NCP + t];
#pragma unroll
            for (int i = 0; i < 5; i++) {
                int n0 = 2 * i, n1 = n0 + 1;
                sA[t][i] = pack2(sb1[n0] + p.x * sW1[n0] + p.y * sW1[10 + n0],
                                 sb1[n1] + p.x * sW1[n1] + p.y * sW1[10 + n1]);
                sB[t][i] = pack2(p.x * sW1[20 + n0] + p.y * sW1[30 + n0],
                                 p.x * sW1[20 + n1] + p.y * sW1[30 + n1]);
            }
            sQp[t] = pack2(0.5f * q.x, 0.5f * q.y);
        }
        // per-thread layer-1 parts for current x
        ull axp[5], bxp[5];
#pragma unroll
        for (int i = 0; i < 5; i++) {
            int n0 = 2 * i, n1 = n0 + 1;
            axp[i] = pack2(sb1[n0] + x.x * sW1[n0] + x.y * sW1[10 + n0],
                           sb1[n1] + x.x * sW1[n1] + x.y * sW1[10 + n1]);
            bxp[i] = pack2(x.x * sW1[20 + n0] + x.y * sW1[30 + n0],
                           x.x * sW1[20 + n1] + x.y * sW1[30 + n1]);
        }
        __syncthreads();

        float vx = 0.f, vy = 0.f;
#pragma unroll 2
        for (int jj = 0; jj < 16; jj++) {
            int j = (jj << 2) | quarter;
            ull u1[5];
#pragma unroll
            for (int i = 0; i < 5; i++) u1[i] = add2(axp[i], sB[j][i]);  // m(x, pj)
            float a0; ull a12;
            mlp2(u1, W2p, b2p, W3c0, W3p12, b3c0, b3p12, a0, a12);
            ull u1c[5];
#pragma unroll
            for (int i = 0; i < 5; i++) u1c[i] = add2(sA[j][i], bxp[i]); // m(pj, x)
            float c0; ull c12;
            mlp2(u1c, W2p, b2p, W3c0, W3p12, b3c0, b3p12, c0, c12);
            float a1, a2, c1, c2;
            unpack2(a12, a1, a2);
            unpack2(c12, c1, c2);
            float s0 = a0 + c0;
            float qx2, qy2; unpack2(sQp[j], qx2, qy2);
            vx = fmaf(ex2f(a1), qx2, vx);
            vx = fmaf(ex2f(c1), qx2, vx);
            vx = fmaf(s0, qy2, vx);
            vy = fmaf(s0, qx2, vy);
            vy = fmaf(ex2f(a2), qy2, vy);
            vy = fmaf(ex2f(c2), qy2, vy);
        }
        vx += __shfl_xor_sync(0xffffffffu, vx, 1);
        vy += __shfl_xor_sync(0xffffffffu, vy, 1);
        vx += __shfl_xor_sync(0xffffffffu, vx, 2);
        vy += __shfl_xor_sync(0xffffffffu, vy, 2);
        x.x = fmaf(DTC, vx, x.x);
        x.y = fmaf(DTC, vy, x.y);
    }
    if (quarter == 0) ((float2*)dout)[b * NTPL + i0] = x;
}

// ------------------------------------------------------------------
extern "C" void kernel_launch(void* const* d_in, const int* in_sizes, int n_in,
                              void* d_out, int out_size) {
    const float* q0  = (const float*)d_in[0];
    const float* tpl = (const float*)d_in[1];
    const float* cp  = (const float*)d_in[2];
    const float* W1  = (const float*)d_in[3];
    const float* b1  = (const float*)d_in[4];
    const float* W2  = (const float*)d_in[5];
    const float* b2  = (const float*)d_in[6];
    const float* W3  = (const float*)d_in[7];
    const float* b3  = (const float*)d_in[8];
    float* out = (float*)d_out;
    (void)in_sizes; (void)n_in; (void)out_size;

    shoot_all<<<512, 128>>>(q0, cp, W1, b1, W2, b2, W3, b3);
    flow_all<<<NB * (NTPL / 32), 128>>>(tpl, out, W1, b1, W2, b2, W3, b3);
}

// round 6
// speedup vs baseline: 1.4755x; 1.0671x over previous
#include <cuda_runtime.h>

#define NB    16
#define NCP   64
#define NTPL  2048
#define HD    10
#define NSTEP 6
#define DTC   0.2f
#define LOG2E 1.4426950408889634f

typedef unsigned long long ull;

// ---- scratch (static device globals; no allocation) ----
__device__ float2 g_P[NSTEP + 1][NB * NCP];
__device__ float2 g_Q[NSTEP + 1][NB * NCP];
__device__ unsigned g_bar_count;   // zero-initialized; self-resetting
__device__ unsigned g_bar_gen;     // monotonically increasing across replays

// ---------------- packed f32x2 helpers ----------------
__device__ __forceinline__ ull pack2(float lo, float hi) {
    ull d; asm("mov.b64 %0, {%1,%2};" : "=l"(d) : "f"(lo), "f"(hi)); return d;
}
__device__ __forceinline__ void unpack2(ull d, float& lo, float& hi) {
    asm("mov.b64 {%0,%1}, %2;" : "=f"(lo), "=f"(hi) : "l"(d));
}
__device__ __forceinline__ ull fma2(ull a, ull b, ull c) {
    ull d; asm("fma.rn.f32x2 %0, %1, %2, %3;" : "=l"(d) : "l"(a), "l"(b), "l"(c)); return d;
}
__device__ __forceinline__ ull add2(ull a, ull b) {
    ull d; asm("add.rn.f32x2 %0, %1, %2;" : "=l"(d) : "l"(a), "l"(b)); return d;
}
__device__ __forceinline__ float tanhfast(float x) {
    float y; asm("tanh.approx.f32 %0, %1;" : "=f"(y) : "f"(x)); return y;
}
__device__ __forceinline__ float ex2f(float x) {
    float y; asm("ex2.approx.f32 %0, %1;" : "=f"(y) : "f"(x)); return y;
}

// ---------------- software grid barrier (all CTAs resident) ----------------
__device__ __forceinline__ void grid_bar() {
    __syncthreads();
    if (threadIdx.x == 0) {
        __threadfence();
        unsigned gen = *(volatile unsigned*)&g_bar_gen;
        unsigned prev = atomicAdd(&g_bar_count, 1u);
        if (prev == gridDim.x - 1) {
            g_bar_count = 0;
            __threadfence();
            atomicExch(&g_bar_gen, gen + 1u);
        } else {
            while (*(volatile unsigned*)&g_bar_gen == gen) { }
            __threadfence();
        }
    }
    __syncthreads();
}

// ------------------------------------------------------------------
// MLP forward + 2-tangent JVP (tangent dirs = rows da, db of W1)
// ------------------------------------------------------------------
__device__ __forceinline__ void mlp_jac(
    float z0, float z1, float z2, float z3, int da, int db,
    const float* __restrict__ sW1, const float* __restrict__ sb1,
    const float* __restrict__ sW2, const float* __restrict__ sb2,
    const float* __restrict__ sW3, const float* __restrict__ sb3,
    float o[3], float ja[3], float jb[3]) {
    float h1[HD], ta[HD], tb[HD];
#pragma unroll
    for (int n = 0; n < HD; n++) {
        float u = sb1[n] + z0 * sW1[n] + z1 * sW1[10 + n] + z2 * sW1[20 + n] + z3 * sW1[30 + n];
        float h = tanhfast(u);
        float g = 1.0f - h * h;
        h1[n] = h;
        ta[n] = g * sW1[da * 10 + n];
        tb[n] = g * sW1[db * 10 + n];
    }
    float u2[HD], s2a[HD], s2b[HD];
#pragma unroll
    for (int m = 0; m < HD; m++) { u2[m] = sb2[m]; s2a[m] = 0.f; s2b[m] = 0.f; }
#pragma unroll
    for (int n = 0; n < HD; n++) {
        float h = h1[n], aa = ta[n], bb = tb[n];
#pragma unroll
        for (int m = 0; m < HD; m++) {
            float w = sW2[n * 10 + m];
            u2[m] += h * w;
            s2a[m] += aa * w;
            s2b[m] += bb * w;
        }
    }
#pragma unroll
    for (int c = 0; c < 3; c++) { o[c] = sb3[c]; ja[c] = 0.f; jb[c] = 0.f; }
#pragma unroll
    for (int m = 0; m < HD; m++) {
        float h = tanhfast(u2[m]);
        float g = 1.0f - h * h;
        float aa = s2a[m] * g, bb = s2b[m] * g;
#pragma unroll
        for (int c = 0; c < 3; c++) {
            float w = sW3[m * 3 + c];
            o[c] += h * w;
            ja[c] += aa * w;
            jb[c] += bb * w;
        }
    }
}

// ------------------------------------------------------------------
// all 6 shooting steps in ONE persistent kernel (512 CTAs x 128 thr).
// ------------------------------------------------------------------
__global__ void __launch_bounds__(128, 4) shoot_all(
    const float* __restrict__ q0, const float* __restrict__ cp,
    const float* __restrict__ W1, const float* __restrict__ b1,
    const float* __restrict__ W2, const float* __restrict__ b2,
    const float* __restrict__ W3, const float* __restrict__ b3) {
    __shared__ float sW1[40], sb1[10], sW2[100], sb2[10], sW3[30], sb3[3];
    __shared__ float red[2][4][4];
    int t = threadIdx.x;
    for (int i = t; i < 40; i += 128) sW1[i] = W1[i];
    for (int i = t; i < 100; i += 128) sW2[i] = W2[i];
    for (int i = t; i < 30; i += 128) sW3[i] = W3[i];
    if (t < 10) { sb1[t] = b1[t]; sb2[t] = b2[t]; }
    if (t < 3) sb3[t] = b3[t];
    __syncthreads();

    int c = blockIdx.x;
    int b = c >> 5;
    int a0 = (c & 31) << 1;
    int j = t & 63, half = t >> 6;
    const float2* cp2 = (const float2*)cp;
    const float2* q02 = (const float2*)q0;

    for (int k = 0; k < NSTEP; k++) {
        float2 pj, qj;
        if (k == 0) { pj = cp2[j]; qj = q02[b * NCP + j]; }
        else        { pj = g_P[k][b * NCP + j]; qj = g_Q[k][b * NCP + j]; }

        float2 pas[2], qas[2];
#pragma unroll
        for (int aa = 0; aa < 2; aa++) {
            int a = a0 + aa;
            float2 pa, qa;
            if (k == 0) { pa = cp2[a]; qa = q02[b * NCP + a]; }
            else        { pa = g_P[k][b * NCP + a]; qa = g_Q[k][b * NCP + a]; }
            pas[aa] = pa; qas[aa] = qa;

            float z0 = half ? pj.x : pa.x, z1 = half ? pj.y : pa.y;
            float z2 = half ? pa.x : pj.x, z3 = half ? pa.y : pj.y;
            int da = half * 2, db = half * 2 + 1;

            float o[3], ja[3], jb[3];
            mlp_jac(z0, z1, z2, z3, da, db, sW1, sb1, sW2, sb2, sW3, sb3, o, ja, jb);

            float ea = __expf(o[1]), eb = __expf(o[2]);
            float vqx = 0.5f * (ea * qj.x + o[0] * qj.y);
            float vqy = 0.5f * (o[0] * qj.x + eb * qj.y);
            float cw = qa.x * qj.y + qa.y * qj.x;
            float w1 = ea * (qa.x * qj.x), w2 = eb * (qa.y * qj.y);
            float gpx = 0.5f * (cw * ja[0] + w1 * ja[1] + w2 * ja[2]);
            float gpy = 0.5f * (cw * jb[0] + w1 * jb[1] + w2 * jb[2]);

#pragma unroll
            for (int off = 16; off > 0; off >>= 1) {
                vqx += __shfl_down_sync(0xffffffffu, vqx, off);
                vqy += __shfl_down_sync(0xffffffffu, vqy, off);
                gpx += __shfl_down_sync(0xffffffffu, gpx, off);
                gpy += __shfl_down_sync(0xffffffffu, gpy, off);
            }
            if ((t & 31) == 0) {
                int w = t >> 5;
                red[aa][w][0] = vqx; red[aa][w][1] = vqy;
                red[aa][w][2] = gpx; red[aa][w][3] = gpy;
            }
        }
        __syncthreads();
        if (t == 0) {
#pragma unroll
            for (int aa = 0; aa < 2; aa++) {
                int a = a0 + aa;
                float VX = red[aa][0][0] + red[aa][1][0] + red[aa][2][0] + red[aa][3][0];
                float VY = red[aa][0][1] + red[aa][1][1] + red[aa][2][1] + red[aa][3][1];
                float GX = red[aa][0][2] + red[aa][1][2] + red[aa][2][2] + red[aa][3][2];
                float GY = red[aa][0][3] + red[aa][1][3] + red[aa][2][3] + red[aa][3][3];
                g_P[k + 1][b * NCP + a] = make_float2(pas[aa].x + DTC * VX, pas[aa].y + DTC * VY);
                g_Q[k + 1][b * NCP + a] = make_float2(qas[aa].x - DTC * GX, qas[aa].y - DTC * GY);
                if (k == 0) {
                    g_P[0][b * NCP + a] = pas[aa];
                    g_Q[0][b * NCP + a] = qas[aa];
                }
            }
        }
        if (k < NSTEP - 1) grid_bar();
    }
}

// ------------------------------------------------------------------
// packed forward MLP: W2 in REGISTERS (hot, 100 fma2-operands/pair);
// layer-3 weights + b2 read from shared (cold: 25 broadcast LDS/mlp).
// W3 cols 1,2 prescaled by log2e so o12 feeds ex2 directly.
// ------------------------------------------------------------------
__device__ __forceinline__ void mlp2s(
    const ull u1p[5], const ull W2p[50],
    const ull* sb2p, const float* sW3c0, const ull* sW3p12,
    float b3c0, ull b3p12,
    float& o0, ull& o12) {
    ull u2p[5];
#pragma unroll
    for (int i = 0; i < 5; i++) u2p[i] = sb2p[i];
#pragma unroll
    for (int i = 0; i < 5; i++) {
        float lo, hi; unpack2(u1p[i], lo, hi);
        float h0 = tanhfast(lo), h1 = tanhfast(hi);
        ull hp0 = pack2(h0, h0), hp1 = pack2(h1, h1);
        int n0 = (2 * i) * 5, n1 = (2 * i + 1) * 5;
#pragma unroll
        for (int m = 0; m < 5; m++) u2p[m] = fma2(hp0, W2p[n0 + m], u2p[m]);
#pragma unroll
        for (int m = 0; m < 5; m++) u2p[m] = fma2(hp1, W2p[n1 + m], u2p[m]);
    }
    o0 = b3c0; o12 = b3p12;
#pragma unroll
    for (int i = 0; i < 5; i++) {
        float lo, hi; unpack2(u2p[i], lo, hi);
        float h0 = tanhfast(lo), h1 = tanhfast(hi);
        ull hp0 = pack2(h0, h0), hp1 = pack2(h1, h1);
        o12 = fma2(hp0, sW3p12[2 * i], o12);
        o12 = fma2(hp1, sW3p12[2 * i + 1], o12);
        o0 = fmaf(h1, sW3c0[2 * i + 1], fmaf(h0, sW3c0[2 * i], o0));
    }
}

// ------------------------------------------------------------------
// all 7 flow steps in ONE kernel: x in registers across steps.
// 64-thread CTAs (16 points x 4 j-splits) for 2-warp occupancy
// granularity: launch_bounds(64,5) -> reg cap 204 -> 10 warps/SM.
// ------------------------------------------------------------------
__global__ void __launch_bounds__(64, 5) flow_all(
    const float* __restrict__ tpl, float* __restrict__ dout,
    const float* __restrict__ W1, const float* __restrict__ b1,
    const float* __restrict__ W2, const float* __restrict__ b2,
    const float* __restrict__ W3, const float* __restrict__ b3) {
    __shared__ ull sA[NCP][5];   // packed b1 + pj.W1[0:2]
    __shared__ ull sB[NCP][5];   // packed      pj.W1[2:4]
    __shared__ ull sQp[NCP];     // packed (0.5*qx, 0.5*qy)
    __shared__ float sW1[40], sb1[10];
    __shared__ float sW3c0[10];  // W3 col 0
    __shared__ ull sW3p12[10];   // W3 cols 1,2 prescaled by log2e
    __shared__ ull sb2p[5];
    int t = threadIdx.x;
    int blk = blockIdx.x;
    int b = blk >> 7;
    int pt0 = (blk & 127) << 4;
    if (t < 40) sW1[t] = W1[t];
    if (t < 10) {
        sb1[t] = b1[t];
        sW3c0[t] = W3[t * 3 + 0];
        sW3p12[t] = pack2(LOG2E * W3[t * 3 + 1], LOG2E * W3[t * 3 + 2]);
    }
    if (t < 5) sb2p[t] = ((const ull*)b2)[t];

    // W2 resident in registers for the whole kernel (hot path)
    const ull* W2v = (const ull*)W2;
    ull W2p[50];
#pragma unroll
    for (int i = 0; i < 50; i++) W2p[i] = __ldg(&W2v[i]);
    float b3c0 = __ldg(&b3[0]);
    ull b3p12 = pack2(LOG2E * __ldg(&b3[1]), LOG2E * __ldg(&b3[2]));

    int lp = t >> 2, quarter = t & 3;
    int i0 = pt0 + lp;
    float2 x = __ldg(&((const float2*)tpl)[i0]);

    for (int k = 0; k <= NSTEP; k++) {
        __syncthreads();   // prior iteration's reads of sA/sB done (and init fills)
        {
            // all 64 threads fill one cp row each
            float2 p = g_P[k][b * NCP + t];
            float2 q = g_Q[k][b * NCP + t];
#pragma unroll
            for (int i = 0; i < 5; i++) {
                int n0 = 2 * i, n1 = n0 + 1;
                sA[t][i] = pack2(sb1[n0] + p.x * sW1[n0] + p.y * sW1[10 + n0],
                                 sb1[n1] + p.x * sW1[n1] + p.y * sW1[10 + n1]);
                sB[t][i] = pack2(p.x * sW1[20 + n0] + p.y * sW1[30 + n0],
                                 p.x * sW1[20 + n1] + p.y * sW1[30 + n1]);
            }
            sQp[t] = pack2(0.5f * q.x, 0.5f * q.y);
        }
        // per-thread layer-1 parts for current x
        ull axp[5], bxp[5];
#pragma unroll
        for (int i = 0; i < 5; i++) {
            int n0 = 2 * i, n1 = n0 + 1;
            axp[i] = pack2(sb1[n0] + x.x * sW1[n0] + x.y * sW1[10 + n0],
                           sb1[n1] + x.x * sW1[n1] + x.y * sW1[10 + n1]);
            bxp[i] = pack2(x.x * sW1[20 + n0] + x.y * sW1[30 + n0],
                           x.x * sW1[20 + n1] + x.y * sW1[30 + n1]);
        }
        __syncthreads();

        float vx = 0.f, vy = 0.f;
#pragma unroll 1
        for (int jj = 0; jj < 16; jj++) {
            int j = (jj << 2) | quarter;
            ull u1[5];
#pragma unroll
            for (int i = 0; i < 5; i++) u1[i] = add2(axp[i], sB[j][i]);  // m(x, pj)
            float a0; ull a12;
            mlp2s(u1, W2p, sb2p, sW3c0, sW3p12, b3c0, b3p12, a0, a12);
            ull u1c[5];
#pragma unroll
            for (int i = 0; i < 5; i++) u1c[i] = add2(sA[j][i], bxp[i]); // m(pj, x)
            float c0; ull c12;
            mlp2s(u1c, W2p, sb2p, sW3c0, sW3p12, b3c0, b3p12, c0, c12);
            float a1, a2, c1, c2;
            unpack2(a12, a1, a2);
            unpack2(c12, c1, c2);
            float s0 = a0 + c0;
            float qx2, qy2; unpack2(sQp[j], qx2, qy2);
            vx = fmaf(ex2f(a1), qx2, vx);
            vx = fmaf(ex2f(c1), qx2, vx);
            vx = fmaf(s0, qy2, vx);
            vy = fmaf(s0, qx2, vy);
            vy = fmaf(ex2f(a2), qy2, vy);
            vy = fmaf(ex2f(c2), qy2, vy);
        }
        // combine the 4 j-splits (adjacent lanes); sum lands in all 4
        vx += __shfl_xor_sync(0xffffffffu, vx, 1);
        vy += __shfl_xor_sync(0xffffffffu, vy, 1);
        vx += __shfl_xor_sync(0xffffffffu, vx, 2);
        vy += __shfl_xor_sync(0xffffffffu, vy, 2);
        x.x = fmaf(DTC, vx, x.x);
        x.y = fmaf(DTC, vy, x.y);
    }
    if (quarter == 0) ((float2*)dout)[b * NTPL + i0] = x;
}

// ------------------------------------------------------------------
extern "C" void kernel_launch(void* const* d_in, const int* in_sizes, int n_in,
                              void* d_out, int out_size) {
    const float* q0  = (const float*)d_in[0];
    const float* tpl = (const float*)d_in[1];
    const float* cp  = (const float*)d_in[2];
    const float* W1  = (const float*)d_in[3];
    const float* b1  = (const float*)d_in[4];
    const float* W2  = (const float*)d_in[5];
    const float* b2  = (const float*)d_in[6];
    const float* W3  = (const float*)d_in[7];
    const float* b3  = (const float*)d_in[8];
    float* out = (float*)d_out;
    (void)in_sizes; (void)n_in; (void)out_size;

    shoot_all<<<512, 128>>>(q0, cp, W1, b1, W2, b2, W3, b3);
    flow_all<<<NB * (NTPL / 16), 64>>>(tpl, out, W1, b1, W2, b2, W3, b3);
}